// round 5
// baseline (speedup 1.0000x reference)
#include <cuda_runtime.h>
#include <cstdint>

// DenselyCnnAttLayer, TMA-pipelined warp-per-row.
// out[b,s,d] = sum_l softmax_m( sum_l' s[b,s,l'] * Ws[s,l',m] )[l] * x_l[b,s,d]
// B=64, S=512, L=6, D=512, fp32. Traffic: 6 reads + 1 write = ~470MB.
//
// R5: decouple load from compute. Each warp owns a private 2-slot smem ring
// (slot = 6 layers x 2KB = 12KB). An elected lane issues cp.async.bulk (1D TMA)
// for row t+2 while the warp computes row t from smem. TMA keeps DRAM saturated
// regardless of warp compute state (fixes R4's load/compute serialization
// without giving up persistence). Producer == consumer warp -> no cross-warp
// sync; slot reuse ordered by program order. 152 CTAs (1/SM, 192KB smem),
// 8 warps/CTA.

#define DD    512
#define LL    6
#define CHNK  4                 // float4 chunks per lane (512/32/4)
#define NW    8                 // warps per CTA
#define NS    2                 // ring slots per warp
#define ROWB  2048              // bytes per (layer,row)
#define SLOTB (LL * ROWB)       // 12288
#define NSM   152
#define SMEM_DATA  (NW * NS * SLOTB)          // 196608
#define SMEM_TOTAL (SMEM_DATA + NW * NS * 8)  // + mbarriers

__device__ __forceinline__ uint32_t smem_u32(const void* p) {
    uint32_t a;
    asm("{ .reg .u64 t; cvta.to.shared.u64 t, %1; cvt.u32.u64 %0, t; }"
        : "=r"(a) : "l"(p));
    return a;
}
__device__ __forceinline__ void mbar_init1(uint32_t mbar) {
    asm volatile("mbarrier.init.shared.b64 [%0], 1;" :: "r"(mbar) : "memory");
}
__device__ __forceinline__ void mbar_expect(uint32_t mbar, uint32_t bytes) {
    asm volatile("mbarrier.arrive.expect_tx.shared.b64 _, [%0], %1;"
                 :: "r"(mbar), "r"(bytes) : "memory");
}
__device__ __forceinline__ void bulk_ld(uint32_t dst, const void* src,
                                        uint32_t bytes, uint32_t mbar) {
    asm volatile(
        "cp.async.bulk.shared::cta.global.mbarrier::complete_tx::bytes "
        "[%0], [%1], %2, [%3];"
        :: "r"(dst), "l"(src), "r"(bytes), "r"(mbar) : "memory");
}
__device__ __forceinline__ void mbar_wait(uint32_t mbar, uint32_t parity) {
    asm volatile(
        "{\n\t"
        ".reg .pred P;\n\t"
        "WAIT_%=:\n\t"
        "mbarrier.try_wait.parity.acquire.cta.shared::cta.b64 P, [%0], %1, 0x989680;\n\t"
        "@P bra DONE_%=;\n\t"
        "bra WAIT_%=;\n\t"
        "DONE_%=:\n\t"
        "}" :: "r"(mbar), "r"(parity) : "memory");
}

__global__ __launch_bounds__(NW * 32, 1)
void dense_att_tma(const float* __restrict__ x0,
                   const float* __restrict__ x1,
                   const float* __restrict__ x2,
                   const float* __restrict__ x3,
                   const float* __restrict__ x4,
                   const float* __restrict__ x5,
                   const float* __restrict__ Ws,   // [S, L, L]
                   float* __restrict__ out,        // [B, S, D]
                   int rows)
{
    extern __shared__ __align__(16) char smem[];
    const int warp = threadIdx.x >> 5;
    const int lane = threadIdx.x & 31;

    const uint32_t smem_base = smem_u32(smem);
    const uint32_t mbar0 = smem_base + SMEM_DATA + (uint32_t)warp * NS * 8;
    const uint32_t dst0  = smem_base + (uint32_t)warp * NS * SLOTB;
    const char* const slot0 = smem + (size_t)warp * NS * SLOTB;

    if (lane == 0) {
        mbar_init1(mbar0);
        mbar_init1(mbar0 + 8);
        asm volatile("fence.proxy.async.shared::cta;" ::: "memory");
    }
    __syncthreads();

    const float* xs[LL] = {x0, x1, x2, x3, x4, x5};
    const int gw   = blockIdx.x * NW + warp;
    const int wtot = gridDim.x * NW;

    int nloc = 0;
    if (gw < rows) nloc = (rows - 1 - gw) / wtot + 1;

    // Prologue: fill both slots.
    if (lane == 0) {
        for (int t = 0; t < NS && t < nloc; t++) {
            const int r = gw + t * wtot;
            mbar_expect(mbar0 + t * 8, SLOTB);
#pragma unroll
            for (int j = 0; j < LL; j++)
                bulk_ld(dst0 + t * SLOTB + j * ROWB,
                        xs[j] + (size_t)r * DD, ROWB, mbar0 + t * 8);
        }
    }

    for (int t = 0; t < nloc; t++) {
        const int s        = t & (NS - 1);
        const uint32_t par = (uint32_t)(t / NS) & 1u;
        const int row      = gw + t * wtot;

        mbar_wait(mbar0 + s * 8, par);

        // Single smem pass into registers + per-layer sums.
        const char* slot = slot0 + s * SLOTB;
        float4 v[LL][CHNK];
        float  p[LL];
#pragma unroll
        for (int j = 0; j < LL; j++) {
            const float4* sp = reinterpret_cast<const float4*>(slot + j * ROWB);
#pragma unroll
            for (int c = 0; c < CHNK; c++) v[j][c] = sp[lane + c * 32];
            float a0 = (v[j][0].x + v[j][0].y) + (v[j][0].z + v[j][0].w);
            float a1 = (v[j][1].x + v[j][1].y) + (v[j][1].z + v[j][1].w);
            float a2 = (v[j][2].x + v[j][2].y) + (v[j][2].z + v[j][2].w);
            float a3 = (v[j][3].x + v[j][3].y) + (v[j][3].z + v[j][3].w);
            p[j] = (a0 + a1) + (a2 + a3);
        }

        // Warp butterfly reduction.
#pragma unroll
        for (int off = 16; off > 0; off >>= 1) {
#pragma unroll
            for (int j = 0; j < LL; j++)
                p[j] += __shfl_xor_sync(0xffffffffu, p[j], off);
        }

        // Redundant per-lane 6x6 projection + softmax (warp-uniform Ws loads).
        const int sidx = row & 511;                    // S = 512
        const float* W = Ws + (size_t)sidx * (LL * LL);
        float logit[LL];
#pragma unroll
        for (int m = 0; m < LL; m++) logit[m] = 0.0f;
#pragma unroll
        for (int l = 0; l < LL; l++) {
            const float sl = p[l];
#pragma unroll
            for (int m = 0; m < LL; m++)
                logit[m] = fmaf(sl, __ldg(W + l * LL + m), logit[m]);
        }
        float mx = logit[0];
#pragma unroll
        for (int m = 1; m < LL; m++) mx = fmaxf(mx, logit[m]);
        float a[LL];
        float den = 0.0f;
#pragma unroll
        for (int m = 0; m < LL; m++) { a[m] = __expf(logit[m] - mx); den += a[m]; }
        const float inv = __frcp_rn(den);
#pragma unroll
        for (int m = 0; m < LL; m++) a[m] *= inv;

        // Weighted combine from registers, 4 coalesced streaming stores.
        const size_t base = (size_t)row * DD + (size_t)lane * 4;
#pragma unroll
        for (int c = 0; c < CHNK; c++) {
            float4 o;
            o.x = o.y = o.z = o.w = 0.0f;
#pragma unroll
            for (int j = 0; j < LL; j++) {
                o.x = fmaf(a[j], v[j][c].x, o.x);
                o.y = fmaf(a[j], v[j][c].y, o.y);
                o.z = fmaf(a[j], v[j][c].z, o.z);
                o.w = fmaf(a[j], v[j][c].w, o.w);
            }
            __stcs(reinterpret_cast<float4*>(out + base + c * 128), o);
        }

        // Refill this slot with row t+NS (payload already in registers;
        // TMA writes land hundreds of cycles after issue).
        const int tn = t + NS;
        if (tn < nloc && lane == 0) {
            const int rn = gw + tn * wtot;
            mbar_expect(mbar0 + s * 8, SLOTB);
#pragma unroll
            for (int j = 0; j < LL; j++)
                bulk_ld(dst0 + s * SLOTB + j * ROWB,
                        xs[j] + (size_t)rn * DD, ROWB, mbar0 + s * 8);
        }
    }
}

extern "C" void kernel_launch(void* const* d_in, const int* in_sizes, int n_in,
                              void* d_out, int out_size)
{
    const float* x0 = (const float*)d_in[0];
    const float* x1 = (const float*)d_in[1];
    const float* x2 = (const float*)d_in[2];
    const float* x3 = (const float*)d_in[3];
    const float* x4 = (const float*)d_in[4];
    const float* x5 = (const float*)d_in[5];
    const float* Ws = (const float*)d_in[6];
    float* out = (float*)d_out;

    const int rows = in_sizes[0] / DD;          // B*S = 32768

    static int smem_set = 0;
    if (!smem_set) {
        cudaFuncSetAttribute(dense_att_tma,
                             cudaFuncAttributeMaxDynamicSharedMemorySize,
                             SMEM_TOTAL);
        smem_set = 1;
    }
    dense_att_tma<<<NSM, NW * 32, SMEM_TOTAL>>>(x0, x1, x2, x3, x4, x5, Ws,
                                                out, rows);
}